// round 10
// baseline (speedup 1.0000x reference)
#include <cuda_runtime.h>
#include <math.h>
#include <stdint.h>

#define T_STEPS 1024
#define HID     256
#define NSPK    1251
#define F_IN    40

// ---------------- device scratch ----------------
// Self-flagging h exchange for layer->layer handoff + classifier input.
// {h, epoch}; epoch == t+1 marks valid. Zero at module load; reinit kernel
// re-zeroes at END of each call.
__device__ float2 g_hx[3][T_STEPS][HID];   // 6 MB

// ---------------- helpers ----------------
__device__ __forceinline__ float poll_h(const float2* p, int epoch) {
    float h; int e;
    do {
        asm volatile("ld.relaxed.gpu.global.v2.b32 {%0,%1}, [%2];"
                     : "=f"(h), "=r"(e) : "l"(p));
    } while (e != epoch);
    return h;
}
__device__ __forceinline__ void pub_h(float2* p, float h, int epoch) {
    asm volatile("st.relaxed.gpu.global.v2.b32 [%0], {%1,%2};"
                 :: "l"(p), "f"(h), "r"(epoch));
}
__device__ __forceinline__ uint32_t smem_u32(const void* p) {
    uint32_t a;
    asm("{ .reg .u64 t; cvta.to.shared.u64 t, %1; cvt.u32.u64 %0, t; }" : "=r"(a) : "l"(p));
    return a;
}
__device__ __forceinline__ uint32_t mapa_u32(uint32_t addr, uint32_t rank) {
    uint32_t r; asm("mapa.shared::cluster.u32 %0, %1, %2;" : "=r"(r) : "r"(addr), "r"(rank));
    return r;
}
__device__ __forceinline__ void ffma2(unsigned long long& acc,
                                      unsigned long long a, unsigned long long b) {
    asm("fma.rn.f32x2 %0, %1, %2, %0;" : "+l"(acc) : "l"(a), "l"(b));
}
__device__ __forceinline__ unsigned long long pack2(float a, float b) {
    unsigned long long v;
    asm("mov.b64 %0, {%1,%2};" : "=l"(v) : "f"(a), "f"(b));
    return v;
}
__device__ __forceinline__ void mbar_wait_parity(uint32_t mbar, uint32_t parity) {
    asm volatile(
        "{\n\t.reg .pred P;\n\t"
        "LAB_WAIT_%=:\n\t"
        "mbarrier.try_wait.parity.acquire.cluster.shared::cta.b64 P, [%0], %1, 0x989680;\n\t"
        "@P bra.uni LAB_DONE_%=;\n\t"
        "bra.uni LAB_WAIT_%=;\n\t"
        "LAB_DONE_%=:\n\t}"
        :: "r"(mbar), "r"(parity) : "memory");
}

// ---------------- reinit: zero exchange buffer for the NEXT call ----------------
__global__ void reinit_epochs_kernel() {
    int i = blockIdx.x * blockDim.x + threadIdx.x;   // 1536*512 = 786432
    ((float2*)g_hx)[i] = make_float2(0.0f, 0.0f);
}

// ---------------- pipelined 3-layer LSTM: cluster-16 DSMEM exchange ----------------
// grid = 48 CTAs x 512 threads, cluster (16,1,1): cluster k = layer k.
// CTA rank c owns 16 hidden units; warp u = unit c*16+u, lane = gate*8+kc.
// Intra-layer h(t-1) all-gather: each warp broadcasts its hn, lanes 0-15 push
// it to all 16 CTAs' h_s[(t+1)&1] via st.shared::cluster, then one per-lane
// remote mbarrier.arrive.release (16 arrivals at 16 peers in one warp-instr).
// Each CTA's mbar expects 256 arrivals; a warp arrives only AFTER its matvec
// read of the old buffer, so phase completion == safe-to-overwrite.
// Layer->layer handoff + classifier feed stay on the global self-flagging path
// (constant pipeline skew, not rate-setting).
extern "C" __global__ void __launch_bounds__(512, 1)
lstm_pipeline_kernel(
    const float* __restrict__ x,
    const float* __restrict__ wih0, const float* __restrict__ whh0,
    const float* __restrict__ bih0, const float* __restrict__ bhh0,
    const float* __restrict__ wih1, const float* __restrict__ whh1,
    const float* __restrict__ bih1, const float* __restrict__ bhh1,
    const float* __restrict__ wih2, const float* __restrict__ whh2,
    const float* __restrict__ bih2, const float* __restrict__ bhh2)
{
    __shared__ float h_s [2][HID];       // own layer h(t-1), parity-buffered (DSMEM target)
    __shared__ float hp_s[2][HID];       // upstream h(t)     (l>0)
    __shared__ float x_s [2][F_IN];      // x[63,t,:]         (l==0)
    __shared__ __align__(8) unsigned long long mbar_sto;

    const int tid  = threadIdx.x;
    const int l    = blockIdx.x >> 4;
    const int c    = blockIdx.x & 15;    // == cluster rank
    const int u    = tid >> 5;           // warp = hidden unit within CTA
    const int lane = tid & 31;
    const int gate = lane >> 3;          // 0..3 (i,f,g,o)
    const int kc   = lane & 7;           // 0..7 k-chunk
    const int grow = gate * 256 + c * 16 + u;        // global gate row

    const float* whh = (l == 0) ? whh0 : (l == 1) ? whh1 : whh2;
    const float* wih = (l == 0) ? wih0 : (l == 1) ? wih1 : wih2;
    const float* bih = (l == 0) ? bih0 : (l == 1) ? bih1 : bih2;
    const float* bhh = (l == 0) ? bhh0 : (l == 1) ? bhh1 : bhh2;

    // W_hh slice: quad q covers floats [32q+4kc, 32q+4kc+4) -> conflict-free LDS.128
    unsigned long long wh[16];
    #pragma unroll
    for (int q = 0; q < 8; q++) {
        const float* pr = whh + grow * HID + 32 * q + 4 * kc;
        wh[2*q]   = *(const unsigned long long*)(pr);
        wh[2*q+1] = *(const unsigned long long*)(pr + 2);
    }
    unsigned long long wi[16];
    float wx[5];
    if (l == 0) {
        #pragma unroll
        for (int j = 0; j < 5; j++) wx[j] = wih[grow * F_IN + kc * 5 + j];
    } else {
        #pragma unroll
        for (int q = 0; q < 8; q++) {
            const float* pr = wih + grow * HID + 32 * q + 4 * kc;
            wi[2*q]   = *(const unsigned long long*)(pr);
            wi[2*q+1] = *(const unsigned long long*)(pr + 2);
        }
    }
    const float brow = bih[grow] + bhh[grow];

    // mbarrier: 256 expected arrivals (16 warps x 16 CTAs)
    const uint32_t mbar = smem_u32(&mbar_sto);
    if (tid == 0)
        asm volatile("mbarrier.init.shared.b64 [%0], 256;" :: "r"(mbar) : "memory");

    // zero read-buffer 0 of h_s
    if (tid < 64) *(float4*)&h_s[0][tid * 4] = make_float4(0.f, 0.f, 0.f, 0.f);

    // remote addresses: lane < 16 pushes this warp's unit to CTA rank==lane
    uint32_t ra0 = 0, ra1 = 0, rbar = 0;
    if (lane < 16) {
        ra0  = mapa_u32(smem_u32(&h_s[0][c * 16 + u]), (uint32_t)lane);
        ra1  = mapa_u32(smem_u32(&h_s[1][c * 16 + u]), (uint32_t)lane);
        rbar = mapa_u32(mbar, (uint32_t)lane);
    }

    float xr = 0.0f;
    if (l == 0 && tid >= 256 && tid < 256 + F_IN)
        xr = x[(63 * T_STEPS + 0) * F_IN + (tid - 256)];

    __syncthreads();
    asm volatile("barrier.cluster.arrive.aligned;" ::: "memory");
    asm volatile("barrier.cluster.wait.aligned;"   ::: "memory");

    float cst = 0.0f;                    // cell state (lane 0 of each warp)
    // nonlinearity constants: gates i,f,o = sig(x); g = tanh(x) = 2*sig(2x)-1
    const float nl_b = (lane == 16) ? 2.0f : 1.0f;
    const bool  is_g = (lane == 16);

    for (int t = 0; t < T_STEPS; t++) {
        const int b = t & 1;

        // ---- stage upstream / x into parity buffer b (overlaps mbar wait) ----
        if (l > 0) {
            if (tid < 256) hp_s[b][tid] = poll_h(&g_hx[l-1][t][tid], t + 1);
        } else {
            const int j = tid - 256;
            if (j >= 0 && j < F_IN) {
                x_s[b][j] = xr;
                if (t + 1 < T_STEPS)
                    xr = x[(63 * T_STEPS + (t + 1)) * F_IN + j];
            }
        }
        // ---- own-layer h(t-1): wait cluster all-gather of step t-1 ----
        if (t > 0) mbar_wait_parity(mbar, (t - 1) & 1);
        __syncthreads();                 // hp_s/x_s visibility across warps

        // ---- matvec: 32-wide k-slice, packed f32x2, 2-way acc split ----
        unsigned long long a0 = 0ULL, a1 = 0ULL;
        {
            const float* hb = &h_s[b][4 * kc];
            #pragma unroll
            for (int q = 0; q < 8; q++) {
                float4 hv = *(const float4*)(hb + 32 * q);
                ffma2(a0, wh[2*q],   pack2(hv.x, hv.y));
                ffma2(a1, wh[2*q+1], pack2(hv.z, hv.w));
            }
        }
        float px = 0.0f;
        if (l > 0) {
            const float* pb = &hp_s[b][4 * kc];
            #pragma unroll
            for (int q = 0; q < 8; q++) {
                float4 hv = *(const float4*)(pb + 32 * q);
                ffma2(a0, wi[2*q],   pack2(hv.x, hv.y));
                ffma2(a1, wi[2*q+1], pack2(hv.z, hv.w));
            }
        } else {
            #pragma unroll
            for (int j = 0; j < 5; j++) px = fmaf(wx[j], x_s[b][kc * 5 + j], px);
        }
        float l0, h0, l1, h1;
        asm("mov.b64 {%0,%1}, %2;" : "=f"(l0), "=f"(h0) : "l"(a0));
        asm("mov.b64 {%0,%1}, %2;" : "=f"(l1), "=f"(h1) : "l"(a1));
        float p = (l0 + h0) + (l1 + h1) + px;

        // kc-reduce within each 8-lane gate group -> lanes {0,8,16,24}
        p += __shfl_xor_sync(0xffffffffu, p, 1);
        p += __shfl_xor_sync(0xffffffffu, p, 2);
        p += __shfl_xor_sync(0xffffffffu, p, 4);
        p += brow;                        // only kc==0 lanes read below

        // unified nonlinearity on the 4 gate lanes simultaneously:
        // sig/ tanh = a*sig(b*x)+c with per-lane constants (2 MUFU warp-instrs)
        float e   = __expf(-nl_b * p);
        float s   = __fdividef(1.0f, 1.0f + e);
        float val = is_g ? (2.0f * s - 1.0f) : s;

        float ff = __shfl_sync(0xffffffffu, val, 8);
        float cc = __shfl_sync(0xffffffffu, val, 16);
        float oo = __shfl_sync(0xffffffffu, val, 24);
        float hn = 0.0f;
        if (lane == 0) {
            cst = ff * cst + val * cc;               // val = i on lane 0
            float e2 = __expf(-2.0f * cst);
            float th = __fdividef(2.0f, 1.0f + e2) - 1.0f;
            hn = oo * th;
        }
        hn = __shfl_sync(0xffffffffu, hn, 0);

        // ---- cluster push: h(t) -> every rank's h_s[(t+1)&1], then arrive ----
        if (lane < 16) {
            uint32_t ra = ((t + 1) & 1) ? ra1 : ra0;
            asm volatile("st.shared::cluster.b32 [%0], %1;"
                         :: "r"(ra), "r"(__float_as_uint(hn)) : "memory");
            asm volatile("mbarrier.arrive.release.cluster.shared::cluster.b64 _, [%0];"
                         :: "r"(rbar) : "memory");
        }
        // ---- global publish for next layer / classifier ----
        if (lane == 0) pub_h(&g_hx[l][t][c * 16 + u], hn, t + 1);
    }

    // keep smem alive until all remote stores of the final step landed
    asm volatile("barrier.cluster.arrive.aligned;" ::: "memory");
    asm volatile("barrier.cluster.wait.aligned;"   ::: "memory");
}

// ---------------- classifier: logits = h2 @ W_lin^T + b, log_softmax ----------------
__global__ __launch_bounds__(512, 1) void classifier_kernel(
    const float* __restrict__ wlin,
    const float* __restrict__ blin,
    float* __restrict__ out)
{
    __shared__ float lg[4 * NSPK];
    __shared__ float hsm[4 * HID];
    __shared__ float rbuf[16];

    const int b    = blockIdx.x;
    const int t0   = b * 4;
    const int tid  = threadIdx.x;
    const int lane = tid & 31;
    const int wd   = tid >> 5;

    for (int i = tid; i < 4 * HID; i += 512)
        hsm[i] = g_hx[2][t0 + (i >> 8)][i & 255].x;
    __syncthreads();

    float hr[4][8];
    #pragma unroll
    for (int t = 0; t < 4; t++)
        #pragma unroll
        for (int j = 0; j < 8; j++) hr[t][j] = hsm[t * HID + lane * 8 + j];

    for (int o = wd; o < NSPK; o += 16) {
        const float4* wp = (const float4*)(wlin + o * HID + lane * 8);
        float4 w0 = wp[0], w1 = wp[1];
        float wv[8] = {w0.x, w0.y, w0.z, w0.w, w1.x, w1.y, w1.z, w1.w};
        float a0 = 0.f, a1 = 0.f, a2 = 0.f, a3 = 0.f;
        #pragma unroll
        for (int j = 0; j < 8; j++) {
            float wj = wv[j];
            a0 = fmaf(wj, hr[0][j], a0);
            a1 = fmaf(wj, hr[1][j], a1);
            a2 = fmaf(wj, hr[2][j], a2);
            a3 = fmaf(wj, hr[3][j], a3);
        }
        #pragma unroll
        for (int off = 16; off > 0; off >>= 1) {
            a0 += __shfl_xor_sync(0xffffffffu, a0, off);
            a1 += __shfl_xor_sync(0xffffffffu, a1, off);
            a2 += __shfl_xor_sync(0xffffffffu, a2, off);
            a3 += __shfl_xor_sync(0xffffffffu, a3, off);
        }
        if (lane == 0) {
            float bb = blin[o];
            lg[0 * NSPK + o] = a0 + bb;
            lg[1 * NSPK + o] = a1 + bb;
            lg[2 * NSPK + o] = a2 + bb;
            lg[3 * NSPK + o] = a3 + bb;
        }
    }
    __syncthreads();

    for (int t = 0; t < 4; t++) {
        float m = -1e30f;
        for (int o = tid; o < NSPK; o += 512) m = fmaxf(m, lg[t * NSPK + o]);
        #pragma unroll
        for (int off = 16; off > 0; off >>= 1)
            m = fmaxf(m, __shfl_xor_sync(0xffffffffu, m, off));
        if (lane == 0) rbuf[wd] = m;
        __syncthreads();
        float mm = rbuf[0];
        #pragma unroll
        for (int i = 1; i < 16; i++) mm = fmaxf(mm, rbuf[i]);
        __syncthreads();

        float s = 0.0f;
        for (int o = tid; o < NSPK; o += 512) s += __expf(lg[t * NSPK + o] - mm);
        #pragma unroll
        for (int off = 16; off > 0; off >>= 1)
            s += __shfl_xor_sync(0xffffffffu, s, off);
        if (lane == 0) rbuf[wd] = s;
        __syncthreads();
        float ss = 0.0f;
        #pragma unroll
        for (int i = 0; i < 16; i++) ss += rbuf[i];
        float lse = mm + logf(ss);

        for (int o = tid; o < NSPK; o += 512)
            out[(size_t)(t0 + t) * NSPK + o] = lg[t * NSPK + o] - lse;
        __syncthreads();
    }
}

// ---------------- launch ----------------
// Order: [lstm, classifier, reinit] — g_hx zero at module load; reinit restores
// zero at end of every call; ncu's captured launch is the LSTM kernel.
extern "C" void kernel_launch(void* const* d_in, const int* in_sizes, int n_in,
                              void* d_out, int out_size)
{
    const float* x    = (const float*)d_in[0];
    const float* wih0 = (const float*)d_in[1];
    const float* whh0 = (const float*)d_in[2];
    const float* bih0 = (const float*)d_in[3];
    const float* bhh0 = (const float*)d_in[4];
    const float* wih1 = (const float*)d_in[5];
    const float* whh1 = (const float*)d_in[6];
    const float* bih1 = (const float*)d_in[7];
    const float* bhh1 = (const float*)d_in[8];
    const float* wih2 = (const float*)d_in[9];
    const float* whh2 = (const float*)d_in[10];
    const float* bih2 = (const float*)d_in[11];
    const float* bhh2 = (const float*)d_in[12];
    const float* wlin = (const float*)d_in[13];
    const float* blin = (const float*)d_in[14];
    float* out = (float*)d_out;

    cudaFuncSetAttribute(lstm_pipeline_kernel,
                         cudaFuncAttributeNonPortableClusterSizeAllowed, 1);

    cudaLaunchConfig_t cfg = {};
    cfg.gridDim  = dim3(48, 1, 1);
    cfg.blockDim = dim3(512, 1, 1);
    cfg.dynamicSmemBytes = 0;
    cfg.stream = 0;
    cudaLaunchAttribute attrs[1];
    attrs[0].id = cudaLaunchAttributeClusterDimension;
    attrs[0].val.clusterDim.x = 16;
    attrs[0].val.clusterDim.y = 1;
    attrs[0].val.clusterDim.z = 1;
    cfg.attrs = attrs;
    cfg.numAttrs = 1;

    cudaLaunchKernelEx(&cfg, lstm_pipeline_kernel, x,
                       wih0, whh0, bih0, bhh0,
                       wih1, whh1, bih1, bhh1,
                       wih2, whh2, bih2, bhh2);

    classifier_kernel<<<256, 512>>>(wlin, blin, out);
    reinit_epochs_kernel<<<1536, 512>>>();
}

// round 11
// speedup vs baseline: 1.8575x; 1.8575x over previous
#include <cuda_runtime.h>
#include <math.h>
#include <stdint.h>

#define T_STEPS 1024
#define HID     256
#define NSPK    1251
#define F_IN    40

// ---------------- device scratch ----------------
// Global self-flagging h exchange, used ONLY for layer->layer handoff and the
// classifier feed (pipeline-skew-hidden). {h, epoch}; epoch == t+1 => valid.
// Zero at module load; reinit kernel re-zeroes at END of every call.
__device__ float2 g_hx[3][T_STEPS][HID];   // 6 MB

// ---------------- helpers ----------------
__device__ __forceinline__ float poll_h(const float2* p, int epoch) {
    float h; int e;
    do {
        asm volatile("ld.relaxed.gpu.global.v2.b32 {%0,%1}, [%2];"
                     : "=f"(h), "=r"(e) : "l"(p));
    } while (e != epoch);
    return h;
}
__device__ __forceinline__ void pub_h(float2* p, float h, int epoch) {
    asm volatile("st.relaxed.gpu.global.v2.b32 [%0], {%1,%2};"
                 :: "l"(p), "f"(h), "r"(epoch));
}
__device__ __forceinline__ uint32_t smem_u32(const void* p) {
    uint32_t a;
    asm("{ .reg .u64 t; cvta.to.shared.u64 t, %1; cvt.u32.u64 %0, t; }" : "=r"(a) : "l"(p));
    return a;
}
__device__ __forceinline__ uint32_t mapa_u32(uint32_t addr, uint32_t rank) {
    uint32_t r; asm("mapa.shared::cluster.u32 %0, %1, %2;" : "=r"(r) : "r"(addr), "r"(rank));
    return r;
}
// poll a LOCAL smem {h, epoch} word (cheap: ~30 cyc per iteration)
__device__ __forceinline__ float poll_local(uint32_t addr, int epoch) {
    uint32_t hb; int e;
    do {
        asm volatile("ld.volatile.shared.v2.b32 {%0,%1}, [%2];"
                     : "=r"(hb), "=r"(e) : "r"(addr));
    } while (e != epoch);
    return __uint_as_float(hb);
}
__device__ __forceinline__ void ffma2(unsigned long long& acc,
                                      unsigned long long a, unsigned long long b) {
    asm("fma.rn.f32x2 %0, %1, %2, %0;" : "+l"(acc) : "l"(a), "l"(b));
}
__device__ __forceinline__ unsigned long long pack2(float a, float b) {
    unsigned long long v;
    asm("mov.b64 %0, {%1,%2};" : "=l"(v) : "f"(a), "f"(b));
    return v;
}
__device__ __forceinline__ unsigned long long pack2u(uint32_t a, uint32_t b) {
    unsigned long long v;
    asm("mov.b64 %0, {%1,%2};" : "=l"(v) : "r"(a), "r"(b));
    return v;
}

// ---------------- reinit: zero global exchange buffer for the NEXT call ----------------
__global__ void reinit_epochs_kernel() {
    int i = blockIdx.x * blockDim.x + threadIdx.x;   // 1536*512 = 786432
    ((float2*)g_hx)[i] = make_float2(0.0f, 0.0f);
}

// ---------------- pipelined 3-layer LSTM: DSMEM push + local poll, NO mbarrier ----------------
// grid = 48 CTAs x 512 threads, cluster (16,1,1): cluster k = layer k.
// CTA rank c owns 16 hidden units; warp u = unit c*16+u, lane = gate*8+kc.
// Intra-layer exchange: producer warp pushes one {h, epoch} 8B word into every
// rank's hx_s[(t+1)&1][c*16+u] (st.shared::cluster.b64, lanes 0-15). Consumers
// poll their LOCAL word, stage into compact h_s, one __syncthreads, matvec.
// Flow control is the recurrence itself: a producer reaches step t+1 (the next
// write to that parity buffer) only after receiving ALL h(t), which every CTA
// publishes only after it consumed h(t-1) from that buffer. No mbarriers.
extern "C" __global__ void __launch_bounds__(512, 1)
lstm_pipeline_kernel(
    const float* __restrict__ x,
    const float* __restrict__ wih0, const float* __restrict__ whh0,
    const float* __restrict__ bih0, const float* __restrict__ bhh0,
    const float* __restrict__ wih1, const float* __restrict__ whh1,
    const float* __restrict__ bih1, const float* __restrict__ bhh1,
    const float* __restrict__ wih2, const float* __restrict__ whh2,
    const float* __restrict__ bih2, const float* __restrict__ bhh2)
{
    __shared__ float2 hx_s[2][HID];      // DSMEM push target {h, epoch}, parity-buffered
    __shared__ float  h_s [2][HID];      // compact staged own-layer h(t-1)
    __shared__ float  hp_s[2][HID];      // upstream h(t)     (l>0)
    __shared__ float  x_s [2][F_IN];     // x[63,t,:]         (l==0)

    const int tid  = threadIdx.x;
    const int l    = blockIdx.x >> 4;
    const int c    = blockIdx.x & 15;    // == cluster rank
    const int u    = tid >> 5;           // warp = hidden unit within CTA
    const int lane = tid & 31;
    const int gate = lane >> 3;          // 0..3 (i,f,g,o)
    const int kc   = lane & 7;           // 0..7 k-chunk
    const int grow = gate * 256 + c * 16 + u;        // global gate row

    const float* whh = (l == 0) ? whh0 : (l == 1) ? whh1 : whh2;
    const float* wih = (l == 0) ? wih0 : (l == 1) ? wih1 : wih2;
    const float* bih = (l == 0) ? bih0 : (l == 1) ? bih1 : bih2;
    const float* bhh = (l == 0) ? bhh0 : (l == 1) ? bhh1 : bhh2;

    // W_hh slice: quad q covers floats [32q+4kc, 32q+4kc+4) -> conflict-free LDS.128
    unsigned long long wh[16];
    #pragma unroll
    for (int q = 0; q < 8; q++) {
        const float* pr = whh + grow * HID + 32 * q + 4 * kc;
        wh[2*q]   = *(const unsigned long long*)(pr);
        wh[2*q+1] = *(const unsigned long long*)(pr + 2);
    }
    unsigned long long wi[16];
    float wx[5];
    if (l == 0) {
        #pragma unroll
        for (int j = 0; j < 5; j++) wx[j] = wih[grow * F_IN + kc * 5 + j];
    } else {
        #pragma unroll
        for (int q = 0; q < 8; q++) {
            const float* pr = wih + grow * HID + 32 * q + 4 * kc;
            wi[2*q]   = *(const unsigned long long*)(pr);
            wi[2*q+1] = *(const unsigned long long*)(pr + 2);
        }
    }
    const float brow = bih[grow] + bhh[grow];

    // zero read-buffer 0 of compact h_s (h(-1) = 0); hx_s needs no init (t=0 skips poll)
    if (tid < 64) *(float4*)&h_s[0][tid * 4] = make_float4(0.f, 0.f, 0.f, 0.f);

    // remote push addresses: lane < 16 pushes this warp's unit word to rank==lane
    uint32_t ra0 = 0, ra1 = 0;
    if (lane < 16) {
        ra0 = mapa_u32(smem_u32(&hx_s[0][c * 16 + u]), (uint32_t)lane);
        ra1 = mapa_u32(smem_u32(&hx_s[1][c * 16 + u]), (uint32_t)lane);
    }
    // local poll address for consumer thread tid<256
    const uint32_t pa0 = smem_u32(&hx_s[0][tid & 255]);
    const uint32_t pa1 = smem_u32(&hx_s[1][tid & 255]);

    float xr = 0.0f;
    if (l == 0 && tid >= 256 && tid < 256 + F_IN)
        xr = x[(63 * T_STEPS + 0) * F_IN + (tid - 256)];

    __syncthreads();
    asm volatile("barrier.cluster.arrive.aligned;" ::: "memory");
    asm volatile("barrier.cluster.wait.aligned;"   ::: "memory");

    float cst = 0.0f;                    // cell state (lane 0 of each warp)
    // gates i,f,o = sig(x); g = tanh(x) = 2*sig(2x)-1 (lane 16)
    const float nl_b = (lane == 16) ? 2.0f : 1.0f;
    const bool  is_g = (lane == 16);

    for (int t = 0; t < T_STEPS; t++) {
        const int b = t & 1;

        // ---- stage inputs into parity buffer b ----
        if (tid < 256) {
            // own-layer h(t-1): poll LOCAL pushed word for epoch t
            if (t > 0) h_s[b][tid] = poll_local(b ? pa1 : pa0, t);
        } else if (l > 0) {
            hp_s[b][tid - 256] = poll_h(&g_hx[l-1][t][tid - 256], t + 1);
        } else {
            const int j = tid - 256;
            if (j < F_IN) {
                x_s[b][j] = xr;
                if (t + 1 < T_STEPS)
                    xr = x[(63 * T_STEPS + (t + 1)) * F_IN + j];
            }
        }
        __syncthreads();                 // the ONLY barrier per step

        // ---- matvec: 32-wide k-slice, packed f32x2, 2-way acc split ----
        unsigned long long a0 = 0ULL, a1 = 0ULL;
        {
            const float* hb = &h_s[b][4 * kc];
            #pragma unroll
            for (int q = 0; q < 8; q++) {
                float4 hv = *(const float4*)(hb + 32 * q);
                ffma2(a0, wh[2*q],   pack2(hv.x, hv.y));
                ffma2(a1, wh[2*q+1], pack2(hv.z, hv.w));
            }
        }
        float px = 0.0f;
        if (l > 0) {
            const float* pb = &hp_s[b][4 * kc];
            #pragma unroll
            for (int q = 0; q < 8; q++) {
                float4 hv = *(const float4*)(pb + 32 * q);
                ffma2(a0, wi[2*q],   pack2(hv.x, hv.y));
                ffma2(a1, wi[2*q+1], pack2(hv.z, hv.w));
            }
        } else {
            #pragma unroll
            for (int j = 0; j < 5; j++) px = fmaf(wx[j], x_s[b][kc * 5 + j], px);
        }
        float l0, h0, l1, h1;
        asm("mov.b64 {%0,%1}, %2;" : "=f"(l0), "=f"(h0) : "l"(a0));
        asm("mov.b64 {%0,%1}, %2;" : "=f"(l1), "=f"(h1) : "l"(a1));
        float p = (l0 + h0) + (l1 + h1) + px;

        // kc-reduce within each 8-lane gate group -> lanes {0,8,16,24}
        p += __shfl_xor_sync(0xffffffffu, p, 1);
        p += __shfl_xor_sync(0xffffffffu, p, 2);
        p += __shfl_xor_sync(0xffffffffu, p, 4);
        p += brow;

        // unified nonlinearity on the 4 gate lanes in parallel
        float e   = __expf(-nl_b * p);
        float s   = __fdividef(1.0f, 1.0f + e);
        float val = is_g ? (2.0f * s - 1.0f) : s;

        float ff = __shfl_sync(0xffffffffu, val, 8);
        float cc = __shfl_sync(0xffffffffu, val, 16);
        float oo = __shfl_sync(0xffffffffu, val, 24);
        float hn = 0.0f;
        if (lane == 0) {
            cst = ff * cst + val * cc;               // val = i on lane 0
            float e2 = __expf(-2.0f * cst);
            float th = __fdividef(2.0f, 1.0f + e2) - 1.0f;
            hn = oo * th;
        }
        hn = __shfl_sync(0xffffffffu, hn, 0);

        // ---- cluster push: {h, epoch=t+1} into every rank's hx_s[(t+1)&1] ----
        if (lane < 16) {
            unsigned long long v = pack2u(__float_as_uint(hn), (uint32_t)(t + 1));
            uint32_t ra = ((t + 1) & 1) ? ra1 : ra0;
            asm volatile("st.shared::cluster.b64 [%0], %1;" :: "r"(ra), "l"(v) : "memory");
        }
        // ---- global publish for next layer / classifier ----
        if (lane == 0) pub_h(&g_hx[l][t][c * 16 + u], hn, t + 1);
    }

    // keep smem alive until all remote stores of the final step landed
    asm volatile("barrier.cluster.arrive.aligned;" ::: "memory");
    asm volatile("barrier.cluster.wait.aligned;"   ::: "memory");
}

// ---------------- classifier: logits = h2 @ W_lin^T + b, log_softmax ----------------
__global__ __launch_bounds__(512, 1) void classifier_kernel(
    const float* __restrict__ wlin,
    const float* __restrict__ blin,
    float* __restrict__ out)
{
    __shared__ float lg[4 * NSPK];
    __shared__ float hsm[4 * HID];
    __shared__ float rbuf[16];

    const int b    = blockIdx.x;
    const int t0   = b * 4;
    const int tid  = threadIdx.x;
    const int lane = tid & 31;
    const int wd   = tid >> 5;

    for (int i = tid; i < 4 * HID; i += 512)
        hsm[i] = g_hx[2][t0 + (i >> 8)][i & 255].x;
    __syncthreads();

    float hr[4][8];
    #pragma unroll
    for (int t = 0; t < 4; t++)
        #pragma unroll
        for (int j = 0; j < 8; j++) hr[t][j] = hsm[t * HID + lane * 8 + j];

    for (int o = wd; o < NSPK; o += 16) {
        const float4* wp = (const float4*)(wlin + o * HID + lane * 8);
        float4 w0 = wp[0], w1 = wp[1];
        float wv[8] = {w0.x, w0.y, w0.z, w0.w, w1.x, w1.y, w1.z, w1.w};
        float a0 = 0.f, a1 = 0.f, a2 = 0.f, a3 = 0.f;
        #pragma unroll
        for (int j = 0; j < 8; j++) {
            float wj = wv[j];
            a0 = fmaf(wj, hr[0][j], a0);
            a1 = fmaf(wj, hr[1][j], a1);
            a2 = fmaf(wj, hr[2][j], a2);
            a3 = fmaf(wj, hr[3][j], a3);
        }
        #pragma unroll
        for (int off = 16; off > 0; off >>= 1) {
            a0 += __shfl_xor_sync(0xffffffffu, a0, off);
            a1 += __shfl_xor_sync(0xffffffffu, a1, off);
            a2 += __shfl_xor_sync(0xffffffffu, a2, off);
            a3 += __shfl_xor_sync(0xffffffffu, a3, off);
        }
        if (lane == 0) {
            float bb = blin[o];
            lg[0 * NSPK + o] = a0 + bb;
            lg[1 * NSPK + o] = a1 + bb;
            lg[2 * NSPK + o] = a2 + bb;
            lg[3 * NSPK + o] = a3 + bb;
        }
    }
    __syncthreads();

    for (int t = 0; t < 4; t++) {
        float m = -1e30f;
        for (int o = tid; o < NSPK; o += 512) m = fmaxf(m, lg[t * NSPK + o]);
        #pragma unroll
        for (int off = 16; off > 0; off >>= 1)
            m = fmaxf(m, __shfl_xor_sync(0xffffffffu, m, off));
        if (lane == 0) rbuf[wd] = m;
        __syncthreads();
        float mm = rbuf[0];
        #pragma unroll
        for (int i = 1; i < 16; i++) mm = fmaxf(mm, rbuf[i]);
        __syncthreads();

        float s = 0.0f;
        for (int o = tid; o < NSPK; o += 512) s += __expf(lg[t * NSPK + o] - mm);
        #pragma unroll
        for (int off = 16; off > 0; off >>= 1)
            s += __shfl_xor_sync(0xffffffffu, s, off);
        if (lane == 0) rbuf[wd] = s;
        __syncthreads();
        float ss = 0.0f;
        #pragma unroll
        for (int i = 0; i < 16; i++) ss += rbuf[i];
        float lse = mm + logf(ss);

        for (int o = tid; o < NSPK; o += 512)
            out[(size_t)(t0 + t) * NSPK + o] = lg[t * NSPK + o] - lse;
        __syncthreads();
    }
}

// ---------------- launch ----------------
// Order: [lstm, classifier, reinit] — g_hx zero at module load; reinit restores
// zero at end of every call; ncu's captured launch is the LSTM kernel.
extern "C" void kernel_launch(void* const* d_in, const int* in_sizes, int n_in,
                              void* d_out, int out_size)
{
    const float* x    = (const float*)d_in[0];
    const float* wih0 = (const float*)d_in[1];
    const float* whh0 = (const float*)d_in[2];
    const float* bih0 = (const float*)d_in[3];
    const float* bhh0 = (const float*)d_in[4];
    const float* wih1 = (const float*)d_in[5];
    const float* whh1 = (const float*)d_in[6];
    const float* bih1 = (const float*)d_in[7];
    const float* bhh1 = (const float*)d_in[8];
    const float* wih2 = (const float*)d_in[9];
    const float* whh2 = (const float*)d_in[10];
    const float* bih2 = (const float*)d_in[11];
    const float* bhh2 = (const float*)d_in[12];
    const float* wlin = (const float*)d_in[13];
    const float* blin = (const float*)d_in[14];
    float* out = (float*)d_out;

    cudaFuncSetAttribute(lstm_pipeline_kernel,
                         cudaFuncAttributeNonPortableClusterSizeAllowed, 1);

    cudaLaunchConfig_t cfg = {};
    cfg.gridDim  = dim3(48, 1, 1);
    cfg.blockDim = dim3(512, 1, 1);
    cfg.dynamicSmemBytes = 0;
    cfg.stream = 0;
    cudaLaunchAttribute attrs[1];
    attrs[0].id = cudaLaunchAttributeClusterDimension;
    attrs[0].val.clusterDim.x = 16;
    attrs[0].val.clusterDim.y = 1;
    attrs[0].val.clusterDim.z = 1;
    cfg.attrs = attrs;
    cfg.numAttrs = 1;

    cudaLaunchKernelEx(&cfg, lstm_pipeline_kernel, x,
                       wih0, whh0, bih0, bhh0,
                       wih1, whh1, bih1, bhh1,
                       wih2, whh2, bih2, bhh2);

    classifier_kernel<<<256, 512>>>(wlin, blin, out);
    reinit_epochs_kernel<<<1536, 512>>>();
}

// round 12
// speedup vs baseline: 2.3042x; 1.2405x over previous
#include <cuda_runtime.h>
#include <math.h>
#include <stdint.h>

#define T_STEPS 1024
#define HID     256
#define NSPK    1251
#define F_IN    40

typedef unsigned long long ull;

// ---------------- device scratch ----------------
// Global self-flagging h exchange: layer->layer handoff + classifier feed.
// {h, epoch}; epoch == t+1 => valid. Zero at load; reinit re-zeroes at END.
__device__ float2 g_hx[3][T_STEPS][HID];   // 6 MB

// ---------------- helpers ----------------
__device__ __forceinline__ float poll_h(const float2* p, int epoch) {
    float h; int e;
    do {
        asm volatile("ld.relaxed.gpu.global.v2.b32 {%0,%1}, [%2];"
                     : "=f"(h), "=r"(e) : "l"(p));
    } while (e != epoch);
    return h;
}
__device__ __forceinline__ void pub_h(float2* p, float h, int epoch) {
    asm volatile("st.relaxed.gpu.global.v2.b32 [%0], {%1,%2};"
                 :: "l"(p), "f"(h), "r"(epoch));
}
__device__ __forceinline__ uint32_t smem_u32(const void* p) {
    uint32_t a;
    asm("{ .reg .u64 t; cvta.to.shared.u64 t, %1; cvt.u32.u64 %0, t; }" : "=r"(a) : "l"(p));
    return a;
}
__device__ __forceinline__ uint32_t mapa_u32(uint32_t addr, uint32_t rank) {
    uint32_t r; asm("mapa.shared::cluster.u32 %0, %1, %2;" : "=r"(r) : "r"(addr), "r"(rank));
    return r;
}
__device__ __forceinline__ float poll_local(uint32_t addr, int epoch) {
    uint32_t hb; int e;
    do {
        asm volatile("ld.volatile.shared.v2.b32 {%0,%1}, [%2];"
                     : "=r"(hb), "=r"(e) : "r"(addr));
    } while (e != epoch);
    return __uint_as_float(hb);
}
__device__ __forceinline__ void ffma2(ull& acc, ull a, ull b) {
    asm("fma.rn.f32x2 %0, %1, %2, %0;" : "+l"(acc) : "l"(a), "l"(b));
}
__device__ __forceinline__ ull pack2(float a, float b) {
    ull v; asm("mov.b64 %0, {%1,%2};" : "=l"(v) : "f"(a), "f"(b)); return v;
}
__device__ __forceinline__ ull pack2u(uint32_t a, uint32_t b) {
    ull v; asm("mov.b64 %0, {%1,%2};" : "=l"(v) : "r"(a), "r"(b)); return v;
}

// ---------------- reinit: zero global exchange buffer for the NEXT call ----------------
__global__ void reinit_epochs_kernel() {
    int i = blockIdx.x * blockDim.x + threadIdx.x;   // 1536*512 = 786432
    ((float2*)g_hx)[i] = make_float2(0.0f, 0.0f);
}

// ---------------- pipelined 3-layer LSTM: consumer/producer split ----------------
// grid 48 x 512, cluster (16,1,1) per layer. CTA rank c owns 16 units.
// Consumers (warps 0-7): warp u -> units {2u,2u+1}; lane = hi*16+gate*4+k4.
//   Per step: poll local hx_s word -> STS h_s[b] -> bar -> W_hh matvec (+xg_s[b])
//   -> reduce -> gates -> DSMEM push {h,epoch} to all ranks -> global publish.
// Producers (warps 8-15): post-bar of step t, poll g_hx[l-1][t+1] (overlapped),
//   named-bar(1,256), compute xg(t+1)=W_ih*h_up+bias -> xg_s[b^1].
//   Prologue computes xg(0). l==0 producers read x[63,t+1] instead.
extern "C" __global__ void __launch_bounds__(512, 1)
lstm_pipeline_kernel(
    const float* __restrict__ x,
    const float* __restrict__ wih0, const float* __restrict__ whh0,
    const float* __restrict__ bih0, const float* __restrict__ bhh0,
    const float* __restrict__ wih1, const float* __restrict__ whh1,
    const float* __restrict__ bih1, const float* __restrict__ bhh1,
    const float* __restrict__ wih2, const float* __restrict__ whh2,
    const float* __restrict__ bih2, const float* __restrict__ bhh2)
{
    __shared__ float2 hx_s[2][HID];      // DSMEM push target {h, epoch}
    __shared__ float  h_s [2][HID];      // staged own-layer h(t-1)
    __shared__ float  hup_s[HID];        // upstream h / x staging (producers)
    __shared__ float  xg_s[2][64];       // input-projection rows (+bias), parity

    const int tid  = threadIdx.x;
    const int l    = blockIdx.x >> 4;
    const int c    = blockIdx.x & 15;    // cluster rank
    const int lane = tid & 31;

    const float* whh = (l == 0) ? whh0 : (l == 1) ? whh1 : whh2;
    const float* wih = (l == 0) ? wih0 : (l == 1) ? wih1 : wih2;
    const float* bih = (l == 0) ? bih0 : (l == 1) ? bih1 : bih2;
    const float* bhh = (l == 0) ? bhh0 : (l == 1) ? bhh1 : bhh2;

    // ======== consumer state (warps 0-7) ========
    ull wh[32];
    uint32_t ra0 = 0, ra1 = 0, pa0 = 0, pa1 = 0;
    int   my_unit = 0, xg_idx = 0, k4c = 0;
    float nl_b = 1.0f;
    bool  is_g = false;
    // ======== producer state (warps 8-15) ========
    ull wi[32];
    float wx[10];
    float pbias = 0.0f;
    int prow = 0, pk4 = 0;

    if (tid < 256) {
        const int u    = tid >> 5;
        const int hi   = lane >> 4;
        const int gate = (lane >> 2) & 3;
        k4c = lane & 3;
        const int ul = 2 * u + hi;
        const int grow = gate * 256 + c * 16 + ul;
        #pragma unroll
        for (int j = 0; j < 16; j++) {
            const float* pr = whh + grow * HID + 16 * j + 4 * k4c;
            wh[2*j]   = *(const ull*)(pr);
            wh[2*j+1] = *(const ull*)(pr + 2);
        }
        my_unit = c * 16 + ul;
        xg_idx  = gate * 16 + ul;
        nl_b = (gate == 2) ? 2.0f : 1.0f;
        is_g = (gate == 2);
        ra0 = mapa_u32(smem_u32(&hx_s[0][my_unit]), (uint32_t)(lane & 15));
        ra1 = mapa_u32(smem_u32(&hx_s[1][my_unit]), (uint32_t)(lane & 15));
        pa0 = smem_u32(&hx_s[0][tid]);
        pa1 = smem_u32(&hx_s[1][tid]);
        if (tid < 64) *(float4*)&h_s[0][tid * 4] = make_float4(0.f, 0.f, 0.f, 0.f);
    } else {
        const int thr = tid - 256;
        prow = thr >> 2;                 // 0..63 gate row
        pk4  = thr & 3;
        const int pgrow = (prow >> 4) * 256 + c * 16 + (prow & 15);
        pbias = bih[pgrow] + bhh[pgrow];
        if (l == 0) {
            #pragma unroll
            for (int j = 0; j < 10; j++) wx[j] = wih[pgrow * F_IN + pk4 * 10 + j];
        } else {
            #pragma unroll
            for (int j = 0; j < 16; j++) {
                const float* pr = wih + pgrow * HID + 16 * j + 4 * pk4;
                wi[2*j]   = *(const ull*)(pr);
                wi[2*j+1] = *(const ull*)(pr + 2);
            }
        }
    }
    __syncthreads();
    asm volatile("barrier.cluster.arrive.aligned;" ::: "memory");
    asm volatile("barrier.cluster.wait.aligned;"   ::: "memory");

    // ---- producer prologue: xg(0) -> xg_s[0] ----
    if (tid >= 256) {
        const int thr = tid - 256;
        if (l == 0) {
            if (thr < F_IN) hup_s[thr] = x[(63 * T_STEPS + 0) * F_IN + thr];
        } else {
            hup_s[thr] = poll_h(&g_hx[l-1][0][thr], 1);
        }
        asm volatile("bar.sync 1, 256;" ::: "memory");
        float p = 0.0f;
        if (l == 0) {
            #pragma unroll
            for (int j = 0; j < 10; j++) p = fmaf(wx[j], hup_s[pk4 * 10 + j], p);
        } else {
            ull a0 = 0ULL, a1 = 0ULL;
            #pragma unroll
            for (int j = 0; j < 16; j++) {
                float4 hv = *(const float4*)&hup_s[16 * j + 4 * pk4];
                ffma2(a0, wi[2*j],   pack2(hv.x, hv.y));
                ffma2(a1, wi[2*j+1], pack2(hv.z, hv.w));
            }
            float q0, q1, q2, q3;
            asm("mov.b64 {%0,%1}, %2;" : "=f"(q0), "=f"(q1) : "l"(a0));
            asm("mov.b64 {%0,%1}, %2;" : "=f"(q2), "=f"(q3) : "l"(a1));
            p = (q0 + q1) + (q2 + q3);
        }
        p += __shfl_xor_sync(0xffffffffu, p, 1);
        p += __shfl_xor_sync(0xffffffffu, p, 2);
        if (pk4 == 0) xg_s[0][prow] = p + pbias;
    }

    float cst = 0.0f;                    // consumer lanes 0/16: cell state

    for (int t = 0; t < T_STEPS; t++) {
        const int b = t & 1;

        // ---- pre-bar: consumers stage own-layer h(t-1) ----
        if (tid < 256 && t > 0)
            h_s[b][tid] = poll_local(b ? pa1 : pa0, t);
        __syncthreads();

        if (tid < 256) {
            // ---- W_hh matvec (critical path only) ----
            ull a0 = 0ULL, a1 = 0ULL;
            #pragma unroll
            for (int j = 0; j < 16; j++) {
                float4 hv = *(const float4*)&h_s[b][16 * j + 4 * k4c];
                ffma2(a0, wh[2*j],   pack2(hv.x, hv.y));
                ffma2(a1, wh[2*j+1], pack2(hv.z, hv.w));
            }
            float q0, q1, q2, q3;
            asm("mov.b64 {%0,%1}, %2;" : "=f"(q0), "=f"(q1) : "l"(a0));
            asm("mov.b64 {%0,%1}, %2;" : "=f"(q2), "=f"(q3) : "l"(a1));
            float p = (q0 + q1) + (q2 + q3);

            p += __shfl_xor_sync(0xffffffffu, p, 1);
            p += __shfl_xor_sync(0xffffffffu, p, 2);
            p += xg_s[b][xg_idx];        // W_ih*h_up + biases (pipelined)

            // unified nonlinearity on all lanes (each lane = its gate)
            float e   = __expf(-nl_b * p);
            float s   = __fdividef(1.0f, 1.0f + e);
            float val = is_g ? (2.0f * s - 1.0f) : s;

            const int base = lane & 16;
            float ff = __shfl_sync(0xffffffffu, val, base + 4);
            float cc = __shfl_sync(0xffffffffu, val, base + 8);
            float oo = __shfl_sync(0xffffffffu, val, base + 12);
            float hn = 0.0f;
            if ((lane & 15) == 0) {
                cst = ff * cst + val * cc;           // val = i on lanes 0/16
                float e2 = __expf(-2.0f * cst);
                float th = __fdividef(2.0f, 1.0f + e2) - 1.0f;
                hn = oo * th;
            }
            hn = __shfl_sync(0xffffffffu, hn, base);

            // DSMEM push: {h, epoch=t+1} -> every rank's hx_s[(t+1)&1][my_unit]
            ull v = pack2u(__float_as_uint(hn), (uint32_t)(t + 1));
            uint32_t ra = ((t + 1) & 1) ? ra1 : ra0;
            asm volatile("st.shared::cluster.b64 [%0], %1;" :: "r"(ra), "l"(v) : "memory");
            // global publish for next layer / classifier
            if ((lane & 15) == 0) pub_h(&g_hx[l][t][my_unit], hn, t + 1);
        } else if (t + 1 < T_STEPS) {
            // ---- producers: xg(t+1) -> xg_s[b^1] (off critical path) ----
            const int thr = tid - 256;
            if (l == 0) {
                if (thr < F_IN) hup_s[thr] = x[(63 * T_STEPS + (t + 1)) * F_IN + thr];
            } else {
                hup_s[thr] = poll_h(&g_hx[l-1][t+1][thr], t + 2);
            }
            asm volatile("bar.sync 1, 256;" ::: "memory");
            float p = 0.0f;
            if (l == 0) {
                #pragma unroll
                for (int j = 0; j < 10; j++) p = fmaf(wx[j], hup_s[pk4 * 10 + j], p);
            } else {
                ull a0 = 0ULL, a1 = 0ULL;
                #pragma unroll
                for (int j = 0; j < 16; j++) {
                    float4 hv = *(const float4*)&hup_s[16 * j + 4 * pk4];
                    ffma2(a0, wi[2*j],   pack2(hv.x, hv.y));
                    ffma2(a1, wi[2*j+1], pack2(hv.z, hv.w));
                }
                float q0, q1, q2, q3;
                asm("mov.b64 {%0,%1}, %2;" : "=f"(q0), "=f"(q1) : "l"(a0));
                asm("mov.b64 {%0,%1}, %2;" : "=f"(q2), "=f"(q3) : "l"(a1));
                p = (q0 + q1) + (q2 + q3);
            }
            p += __shfl_xor_sync(0xffffffffu, p, 1);
            p += __shfl_xor_sync(0xffffffffu, p, 2);
            if (pk4 == 0) xg_s[b ^ 1][prow] = p + pbias;
        }
    }

    asm volatile("barrier.cluster.arrive.aligned;" ::: "memory");
    asm volatile("barrier.cluster.wait.aligned;"   ::: "memory");
}

// ---------------- classifier: logits = h2 @ W_lin^T + b, log_softmax ----------------
__global__ __launch_bounds__(512, 1) void classifier_kernel(
    const float* __restrict__ wlin,
    const float* __restrict__ blin,
    float* __restrict__ out)
{
    __shared__ float lg[4 * NSPK];
    __shared__ float hsm[4 * HID];
    __shared__ float rbuf[16];

    const int b    = blockIdx.x;
    const int t0   = b * 4;
    const int tid  = threadIdx.x;
    const int lane = tid & 31;
    const int wd   = tid >> 5;

    for (int i = tid; i < 4 * HID; i += 512)
        hsm[i] = g_hx[2][t0 + (i >> 8)][i & 255].x;
    __syncthreads();

    float hr[4][8];
    #pragma unroll
    for (int t = 0; t < 4; t++)
        #pragma unroll
        for (int j = 0; j < 8; j++) hr[t][j] = hsm[t * HID + lane * 8 + j];

    for (int o = wd; o < NSPK; o += 16) {
        const float4* wp = (const float4*)(wlin + o * HID + lane * 8);
        float4 w0 = wp[0], w1 = wp[1];
        float wv[8] = {w0.x, w0.y, w0.z, w0.w, w1.x, w1.y, w1.z, w1.w};
        float a0 = 0.f, a1 = 0.f, a2 = 0.f, a3 = 0.f;
        #pragma unroll
        for (int j = 0; j < 8; j++) {
            float wj = wv[j];
            a0 = fmaf(wj, hr[0][j], a0);
            a1 = fmaf(wj, hr[1][j], a1);
            a2 = fmaf(wj, hr[2][j], a2);
            a3 = fmaf(wj, hr[3][j], a3);
        }
        #pragma unroll
        for (int off = 16; off > 0; off >>= 1) {
            a0 += __shfl_xor_sync(0xffffffffu, a0, off);
            a1 += __shfl_xor_sync(0xffffffffu, a1, off);
            a2 += __shfl_xor_sync(0xffffffffu, a2, off);
            a3 += __shfl_xor_sync(0xffffffffu, a3, off);
        }
        if (lane == 0) {
            float bb = blin[o];
            lg[0 * NSPK + o] = a0 + bb;
            lg[1 * NSPK + o] = a1 + bb;
            lg[2 * NSPK + o] = a2 + bb;
            lg[3 * NSPK + o] = a3 + bb;
        }
    }
    __syncthreads();

    for (int t = 0; t < 4; t++) {
        float m = -1e30f;
        for (int o = tid; o < NSPK; o += 512) m = fmaxf(m, lg[t * NSPK + o]);
        #pragma unroll
        for (int off = 16; off > 0; off >>= 1)
            m = fmaxf(m, __shfl_xor_sync(0xffffffffu, m, off));
        if (lane == 0) rbuf[wd] = m;
        __syncthreads();
        float mm = rbuf[0];
        #pragma unroll
        for (int i = 1; i < 16; i++) mm = fmaxf(mm, rbuf[i]);
        __syncthreads();

        float s = 0.0f;
        for (int o = tid; o < NSPK; o += 512) s += __expf(lg[t * NSPK + o] - mm);
        #pragma unroll
        for (int off = 16; off > 0; off >>= 1)
            s += __shfl_xor_sync(0xffffffffu, s, off);
        if (lane == 0) rbuf[wd] = s;
        __syncthreads();
        float ss = 0.0f;
        #pragma unroll
        for (int i = 0; i < 16; i++) ss += rbuf[i];
        float lse = mm + logf(ss);

        for (int o = tid; o < NSPK; o += 512)
            out[(size_t)(t0 + t) * NSPK + o] = lg[t * NSPK + o] - lse;
        __syncthreads();
    }
}

// ---------------- launch ----------------
extern "C" void kernel_launch(void* const* d_in, const int* in_sizes, int n_in,
                              void* d_out, int out_size)
{
    const float* x    = (const float*)d_in[0];
    const float* wih0 = (const float*)d_in[1];
    const float* whh0 = (const float*)d_in[2];
    const float* bih0 = (const float*)d_in[3];
    const float* bhh0 = (const float*)d_in[4];
    const float* wih1 = (const float*)d_in[5];
    const float* whh1 = (const float*)d_in[6];
    const float* bih1 = (const float*)d_in[7];
    const float* bhh1 = (const float*)d_in[8];
    const float* wih2 = (const float*)d_in[9];
    const float* whh2 = (const float*)d_in[10];
    const float* bih2 = (const float*)d_in[11];
    const float* bhh2 = (const float*)d_in[12];
    const float* wlin = (const float*)d_in[13];
    const float* blin = (const float*)d_in[14];
    float* out = (float*)d_out;

    cudaFuncSetAttribute(lstm_pipeline_kernel,
                         cudaFuncAttributeNonPortableClusterSizeAllowed, 1);

    cudaLaunchConfig_t cfg = {};
    cfg.gridDim  = dim3(48, 1, 1);
    cfg.blockDim = dim3(512, 1, 1);
    cfg.dynamicSmemBytes = 0;
    cfg.stream = 0;
    cudaLaunchAttribute attrs[1];
    attrs[0].id = cudaLaunchAttributeClusterDimension;
    attrs[0].val.clusterDim.x = 16;
    attrs[0].val.clusterDim.y = 1;
    attrs[0].val.clusterDim.z = 1;
    cfg.attrs = attrs;
    cfg.numAttrs = 1;

    cudaLaunchKernelEx(&cfg, lstm_pipeline_kernel, x,
                       wih0, whh0, bih0, bhh0,
                       wih1, whh1, bih1, bhh1,
                       wih2, whh2, bih2, bhh2);

    classifier_kernel<<<256, 512>>>(wlin, blin, out);
    reinit_epochs_kernel<<<1536, 512>>>();
}

// round 13
// speedup vs baseline: 2.4262x; 1.0529x over previous
#include <cuda_runtime.h>
#include <math.h>
#include <stdint.h>

#define T_STEPS 1024
#define HID     256
#define NSPK    1251
#define F_IN    40

typedef unsigned long long ull;

// ---------------- device scratch ----------------
// Global self-flagging h exchange: layer->layer handoff + classifier feed.
// {h, epoch}; epoch == t+1 => valid. Zero at load; reinit re-zeroes at END.
__device__ float2 g_hx[3][T_STEPS][HID];   // 6 MB

// ---------------- helpers ----------------
__device__ __forceinline__ float poll_h(const float2* p, int epoch) {
    float h; int e;
    do {
        asm volatile("ld.relaxed.gpu.global.v2.b32 {%0,%1}, [%2];"
                     : "=f"(h), "=r"(e) : "l"(p));
    } while (e != epoch);
    return h;
}
__device__ __forceinline__ void pub_h(float2* p, float h, int epoch) {
    asm volatile("st.relaxed.gpu.global.v2.b32 [%0], {%1,%2};"
                 :: "l"(p), "f"(h), "r"(epoch));
}
__device__ __forceinline__ uint32_t smem_u32(const void* p) {
    uint32_t a;
    asm("{ .reg .u64 t; cvta.to.shared.u64 t, %1; cvt.u32.u64 %0, t; }" : "=r"(a) : "l"(p));
    return a;
}
__device__ __forceinline__ uint32_t mapa_u32(uint32_t addr, uint32_t rank) {
    uint32_t r; asm("mapa.shared::cluster.u32 %0, %1, %2;" : "=r"(r) : "r"(addr), "r"(rank));
    return r;
}
// poll a LOCAL smem {val, epoch} word
__device__ __forceinline__ float poll_local(uint32_t addr, int epoch) {
    uint32_t hb; int e;
    do {
        asm volatile("ld.volatile.shared.v2.b32 {%0,%1}, [%2];"
                     : "=r"(hb), "=r"(e) : "r"(addr));
    } while (e != epoch);
    return __uint_as_float(hb);
}
__device__ __forceinline__ void st_local2(uint32_t addr, float v, int epoch) {
    asm volatile("st.volatile.shared.v2.b32 [%0], {%1,%2};"
                 :: "r"(addr), "r"(__float_as_uint(v)), "r"(epoch) : "memory");
}
__device__ __forceinline__ int ld_local(uint32_t addr) {
    int v; asm volatile("ld.volatile.shared.b32 %0, [%1];" : "=r"(v) : "r"(addr));
    return v;
}
__device__ __forceinline__ void st_local(uint32_t addr, int v) {
    asm volatile("st.volatile.shared.b32 [%0], %1;" :: "r"(addr), "r"(v) : "memory");
}
__device__ __forceinline__ void ffma2(ull& acc, ull a, ull b) {
    asm("fma.rn.f32x2 %0, %1, %2, %0;" : "+l"(acc) : "l"(a), "l"(b));
}
__device__ __forceinline__ ull pack2(float a, float b) {
    ull v; asm("mov.b64 %0, {%1,%2};" : "=l"(v) : "f"(a), "f"(b)); return v;
}
__device__ __forceinline__ ull pack2u(uint32_t a, uint32_t b) {
    ull v; asm("mov.b64 %0, {%1,%2};" : "=l"(v) : "r"(a), "r"(b)); return v;
}

// ---------------- reinit: zero global exchange buffer for the NEXT call ----------------
__global__ void reinit_epochs_kernel() {
    int i = blockIdx.x * blockDim.x + threadIdx.x;   // 1536*512 = 786432
    ((float2*)g_hx)[i] = make_float2(0.0f, 0.0f);
}

// ---------------- pipelined 3-layer LSTM: fully decoupled consumer/producer ----------------
// grid 48 x 512, cluster (16,1,1) per layer; CTA rank c owns 16 units.
// Consumers (warps 0-7, bar 2 only): poll local hx word -> h_s[b] -> bar2 ->
//   W_hh matvec -> poll xg word (steady-state hit) -> gates -> DSMEM push ->
//   global publish. cons_step smem word advertises progress.
// Producers (warps 8-15, bar 1 only): stage upstream h / x (double-buffered
//   hup_s) -> bar1 -> W_ih matvec -> backpressure on cons_step -> write
//   self-flagging xg word. NEVER rendezvous with consumers.
extern "C" __global__ void __launch_bounds__(512, 1)
lstm_pipeline_kernel(
    const float* __restrict__ x,
    const float* __restrict__ wih0, const float* __restrict__ whh0,
    const float* __restrict__ bih0, const float* __restrict__ bhh0,
    const float* __restrict__ wih1, const float* __restrict__ whh1,
    const float* __restrict__ bih1, const float* __restrict__ bhh1,
    const float* __restrict__ wih2, const float* __restrict__ whh2,
    const float* __restrict__ bih2, const float* __restrict__ bhh2)
{
    __shared__ float2 hx_s[2][HID];      // DSMEM push target {h, epoch}
    __shared__ float  h_s [2][HID];      // staged own-layer h(t-1)
    __shared__ float  hup_s[2][HID];     // upstream h / x staging (double-buffered)
    __shared__ float2 xg_s[2][68];       // {xg row val, epoch}, stride 17 (bank-spread)
    __shared__ int    cons_step_sto;     // consumer progress (volatile)

    const int tid  = threadIdx.x;
    const int l    = blockIdx.x >> 4;
    const int c    = blockIdx.x & 15;    // cluster rank
    const int lane = tid & 31;

    const float* whh = (l == 0) ? whh0 : (l == 1) ? whh1 : whh2;
    const float* wih = (l == 0) ? wih0 : (l == 1) ? wih1 : wih2;
    const float* bih = (l == 0) ? bih0 : (l == 1) ? bih1 : bih2;
    const float* bhh = (l == 0) ? bhh0 : (l == 1) ? bhh1 : bhh2;

    const uint32_t cons_step = smem_u32(&cons_step_sto);

    // ======== consumer state ========
    ull wh[32];
    uint32_t ra0 = 0, ra1 = 0, pa0 = 0, pa1 = 0, xga0 = 0, xga1 = 0;
    int   my_unit = 0, k4c = 0;
    float nl_b = 1.0f;
    bool  is_g = false;
    // ======== producer state ========
    ull wi[32];
    float wx[10];
    float pbias = 0.0f;
    int prow = 0, pk4 = 0;
    uint32_t xw0 = 0, xw1 = 0;

    if (tid < 256) {
        const int u    = tid >> 5;
        const int hi   = lane >> 4;
        const int gate = (lane >> 2) & 3;
        k4c = lane & 3;
        const int ul = 2 * u + hi;
        const int grow = gate * 256 + c * 16 + ul;
        #pragma unroll
        for (int j = 0; j < 16; j++) {
            const float* pr = whh + grow * HID + 16 * j + 4 * k4c;
            wh[2*j]   = *(const ull*)(pr);
            wh[2*j+1] = *(const ull*)(pr + 2);
        }
        my_unit = c * 16 + ul;
        nl_b = (gate == 2) ? 2.0f : 1.0f;
        is_g = (gate == 2);
        ra0 = mapa_u32(smem_u32(&hx_s[0][my_unit]), (uint32_t)(lane & 15));
        ra1 = mapa_u32(smem_u32(&hx_s[1][my_unit]), (uint32_t)(lane & 15));
        pa0 = smem_u32(&hx_s[0][tid]);
        pa1 = smem_u32(&hx_s[1][tid]);
        const int xgi = gate * 17 + ul;
        xga0 = smem_u32(&xg_s[0][xgi]);
        xga1 = smem_u32(&xg_s[1][xgi]);
        if (tid < 64) *(float4*)&h_s[0][tid * 4] = make_float4(0.f, 0.f, 0.f, 0.f);
        if (tid == 0) st_local(cons_step, -1);
    } else {
        const int thr = tid - 256;
        prow = thr >> 2;                 // 0..63 gate row
        pk4  = thr & 3;
        const int pgrow = (prow >> 4) * 256 + c * 16 + (prow & 15);
        pbias = bih[pgrow] + bhh[pgrow];
        const int xgi = (prow >> 4) * 17 + (prow & 15);
        xw0 = smem_u32(&xg_s[0][xgi]);
        xw1 = smem_u32(&xg_s[1][xgi]);
        if (l == 0) {
            #pragma unroll
            for (int j = 0; j < 10; j++) wx[j] = wih[pgrow * F_IN + pk4 * 10 + j];
        } else {
            #pragma unroll
            for (int j = 0; j < 16; j++) {
                const float* pr = wih + pgrow * HID + 16 * j + 4 * pk4;
                wi[2*j]   = *(const ull*)(pr);
                wi[2*j+1] = *(const ull*)(pr + 2);
            }
        }
    }
    __syncthreads();
    asm volatile("barrier.cluster.arrive.aligned;" ::: "memory");
    asm volatile("barrier.cluster.wait.aligned;"   ::: "memory");

    if (tid < 256) {
        // ==================== CONSUMER LOOP ====================
        float cst = 0.0f;                // lanes 0/16: cell state
        for (int t = 0; t < T_STEPS; t++) {
            const int b = t & 1;
            if (t > 0) h_s[b][tid] = poll_local(b ? pa1 : pa0, t);
            asm volatile("bar.sync 2, 256;" ::: "memory");
            if (tid == 0) st_local(cons_step, t);

            // W_hh matvec
            ull a0 = 0ULL, a1 = 0ULL;
            #pragma unroll
            for (int j = 0; j < 16; j++) {
                float4 hv = *(const float4*)&h_s[b][16 * j + 4 * k4c];
                ffma2(a0, wh[2*j],   pack2(hv.x, hv.y));
                ffma2(a1, wh[2*j+1], pack2(hv.z, hv.w));
            }
            float q0, q1, q2, q3;
            asm("mov.b64 {%0,%1}, %2;" : "=f"(q0), "=f"(q1) : "l"(a0));
            asm("mov.b64 {%0,%1}, %2;" : "=f"(q2), "=f"(q3) : "l"(a1));
            float p = (q0 + q1) + (q2 + q3);
            p += __shfl_xor_sync(0xffffffffu, p, 1);
            p += __shfl_xor_sync(0xffffffffu, p, 2);

            // xg: self-flagging word; steady-state = immediate hit
            p += poll_local(b ? xga1 : xga0, t + 1);

            // unified nonlinearity (each lane = its gate)
            float e   = __expf(-nl_b * p);
            float s   = __fdividef(1.0f, 1.0f + e);
            float val = is_g ? (2.0f * s - 1.0f) : s;

            const int base = lane & 16;
            float ff = __shfl_sync(0xffffffffu, val, base + 4);
            float cc = __shfl_sync(0xffffffffu, val, base + 8);
            float oo = __shfl_sync(0xffffffffu, val, base + 12);
            float hn = 0.0f;
            if ((lane & 15) == 0) {
                cst = ff * cst + val * cc;           // val = i on lanes 0/16
                float e2 = __expf(-2.0f * cst);
                float th = __fdividef(2.0f, 1.0f + e2) - 1.0f;
                hn = oo * th;
            }
            hn = __shfl_sync(0xffffffffu, hn, base);

            // DSMEM push {h, epoch=t+1} to every rank; then global publish
            ull v = pack2u(__float_as_uint(hn), (uint32_t)(t + 1));
            uint32_t ra = ((t + 1) & 1) ? ra1 : ra0;
            asm volatile("st.shared::cluster.b64 [%0], %1;" :: "r"(ra), "l"(v) : "memory");
            if ((lane & 15) == 0) pub_h(&g_hx[l][t][my_unit], hn, t + 1);
        }
    } else {
        // ==================== PRODUCER LOOP ====================
        const int thr = tid - 256;
        float xr = 0.0f;
        if (l == 0 && thr < F_IN) xr = x[(63 * T_STEPS + 0) * F_IN + thr];

        for (int t = 0; t < T_STEPS; t++) {
            const int b = t & 1;
            // stage upstream h(t) / x(t) into hup_s[b]
            if (l == 0) {
                if (thr < F_IN) {
                    hup_s[b][thr] = xr;
                    if (t + 1 < T_STEPS)
                        xr = x[(63 * T_STEPS + (t + 1)) * F_IN + thr];  // prefetch
                }
            } else {
                hup_s[b][thr] = poll_h(&g_hx[l-1][t][thr], t + 1);
            }
            asm volatile("bar.sync 1, 256;" ::: "memory");

            // W_ih matvec
            float p = 0.0f;
            if (l == 0) {
                #pragma unroll
                for (int j = 0; j < 10; j++) p = fmaf(wx[j], hup_s[b][pk4 * 10 + j], p);
            } else {
                ull a0 = 0ULL, a1 = 0ULL;
                #pragma unroll
                for (int j = 0; j < 16; j++) {
                    float4 hv = *(const float4*)&hup_s[b][16 * j + 4 * pk4];
                    ffma2(a0, wi[2*j],   pack2(hv.x, hv.y));
                    ffma2(a1, wi[2*j+1], pack2(hv.z, hv.w));
                }
                float q0, q1, q2, q3;
                asm("mov.b64 {%0,%1}, %2;" : "=f"(q0), "=f"(q1) : "l"(a0));
                asm("mov.b64 {%0,%1}, %2;" : "=f"(q2), "=f"(q3) : "l"(a1));
                p = (q0 + q1) + (q2 + q3);
            }
            p += __shfl_xor_sync(0xffffffffu, p, 1);
            p += __shfl_xor_sync(0xffffffffu, p, 2);

            if (pk4 == 0) {
                // backpressure: slot t&1 holds xg(t-2); consumers must have
                // finished step t-2 (cons_step >= t-1) before we overwrite
                if (t >= 2) { while (ld_local(cons_step) < t - 1) {} }
                st_local2(b ? xw1 : xw0, p + pbias, t + 1);
            }
        }
    }

    asm volatile("barrier.cluster.arrive.aligned;" ::: "memory");
    asm volatile("barrier.cluster.wait.aligned;"   ::: "memory");
}

// ---------------- classifier: logits = h2 @ W_lin^T + b, log_softmax ----------------
__global__ __launch_bounds__(512, 1) void classifier_kernel(
    const float* __restrict__ wlin,
    const float* __restrict__ blin,
    float* __restrict__ out)
{
    __shared__ float lg[4 * NSPK];
    __shared__ float hsm[4 * HID];
    __shared__ float rbuf[16];

    const int b    = blockIdx.x;
    const int t0   = b * 4;
    const int tid  = threadIdx.x;
    const int lane = tid & 31;
    const int wd   = tid >> 5;

    for (int i = tid; i < 4 * HID; i += 512)
        hsm[i] = g_hx[2][t0 + (i >> 8)][i & 255].x;
    __syncthreads();

    float hr[4][8];
    #pragma unroll
    for (int t = 0; t < 4; t++)
        #pragma unroll
        for (int j = 0; j < 8; j++) hr[t][j] = hsm[t * HID + lane * 8 + j];

    for (int o = wd; o < NSPK; o += 16) {
        const float4* wp = (const float4*)(wlin + o * HID + lane * 8);
        float4 w0 = wp[0], w1 = wp[1];
        float wv[8] = {w0.x, w0.y, w0.z, w0.w, w1.x, w1.y, w1.z, w1.w};
        float a0 = 0.f, a1 = 0.f, a2 = 0.f, a3 = 0.f;
        #pragma unroll
        for (int j = 0; j < 8; j++) {
            float wj = wv[j];
            a0 = fmaf(wj, hr[0][j], a0);
            a1 = fmaf(wj, hr[1][j], a1);
            a2 = fmaf(wj, hr[2][j], a2);
            a3 = fmaf(wj, hr[3][j], a3);
        }
        #pragma unroll
        for (int off = 16; off > 0; off >>= 1) {
            a0 += __shfl_xor_sync(0xffffffffu, a0, off);
            a1 += __shfl_xor_sync(0xffffffffu, a1, off);
            a2 += __shfl_xor_sync(0xffffffffu, a2, off);
            a3 += __shfl_xor_sync(0xffffffffu, a3, off);
        }
        if (lane == 0) {
            float bb = blin[o];
            lg[0 * NSPK + o] = a0 + bb;
            lg[1 * NSPK + o] = a1 + bb;
            lg[2 * NSPK + o] = a2 + bb;
            lg[3 * NSPK + o] = a3 + bb;
        }
    }
    __syncthreads();

    for (int t = 0; t < 4; t++) {
        float m = -1e30f;
        for (int o = tid; o < NSPK; o += 512) m = fmaxf(m, lg[t * NSPK + o]);
        #pragma unroll
        for (int off = 16; off > 0; off >>= 1)
            m = fmaxf(m, __shfl_xor_sync(0xffffffffu, m, off));
        if (lane == 0) rbuf[wd] = m;
        __syncthreads();
        float mm = rbuf[0];
        #pragma unroll
        for (int i = 1; i < 16; i++) mm = fmaxf(mm, rbuf[i]);
        __syncthreads();

        float s = 0.0f;
        for (int o = tid; o < NSPK; o += 512) s += __expf(lg[t * NSPK + o] - mm);
        #pragma unroll
        for (int off = 16; off > 0; off >>= 1)
            s += __shfl_xor_sync(0xffffffffu, s, off);
        if (lane == 0) rbuf[wd] = s;
        __syncthreads();
        float ss = 0.0f;
        #pragma unroll
        for (int i = 0; i < 16; i++) ss += rbuf[i];
        float lse = mm + logf(ss);

        for (int o = tid; o < NSPK; o += 512)
            out[(size_t)(t0 + t) * NSPK + o] = lg[t * NSPK + o] - lse;
        __syncthreads();
    }
}

// ---------------- launch ----------------
extern "C" void kernel_launch(void* const* d_in, const int* in_sizes, int n_in,
                              void* d_out, int out_size)
{
    const float* x    = (const float*)d_in[0];
    const float* wih0 = (const float*)d_in[1];
    const float* whh0 = (const float*)d_in[2];
    const float* bih0 = (const float*)d_in[3];
    const float* bhh0 = (const float*)d_in[4];
    const float* wih1 = (const float*)d_in[5];
    const float* whh1 = (const float*)d_in[6];
    const float* bih1 = (const float*)d_in[7];
    const float* bhh1 = (const float*)d_in[8];
    const float* wih2 = (const float*)d_in[9];
    const float* whh2 = (const float*)d_in[10];
    const float* bih2 = (const float*)d_in[11];
    const float* bhh2 = (const float*)d_in[12];
    const float* wlin = (const float*)d_in[13];
    const float* blin = (const float*)d_in[14];
    float* out = (float*)d_out;

    cudaFuncSetAttribute(lstm_pipeline_kernel,
                         cudaFuncAttributeNonPortableClusterSizeAllowed, 1);

    cudaLaunchConfig_t cfg = {};
    cfg.gridDim  = dim3(48, 1, 1);
    cfg.blockDim = dim3(512, 1, 1);
    cfg.dynamicSmemBytes = 0;
    cfg.stream = 0;
    cudaLaunchAttribute attrs[1];
    attrs[0].id = cudaLaunchAttributeClusterDimension;
    attrs[0].val.clusterDim.x = 16;
    attrs[0].val.clusterDim.y = 1;
    attrs[0].val.clusterDim.z = 1;
    cfg.attrs = attrs;
    cfg.numAttrs = 1;

    cudaLaunchKernelEx(&cfg, lstm_pipeline_kernel, x,
                       wih0, whh0, bih0, bhh0,
                       wih1, whh1, bih1, bhh1,
                       wih2, whh2, bih2, bhh2);

    classifier_kernel<<<256, 512>>>(wlin, blin, out);
    reinit_epochs_kernel<<<1536, 512>>>();
}

// round 14
// speedup vs baseline: 2.5233x; 1.0400x over previous
#include <cuda_runtime.h>
#include <math.h>
#include <stdint.h>

#define T_STEPS 1024
#define HID     256
#define NSPK    1251
#define F_IN    40

typedef unsigned long long ull;

// ---------------- device scratch ----------------
// Global self-flagging h exchange: layer->layer handoff + classifier feed.
// {h, epoch}; epoch == t+1 => valid. Zero at load; reinit re-zeroes at END.
__device__ float2 g_hx[3][T_STEPS][HID];   // 6 MB

// ---------------- helpers ----------------
__device__ __forceinline__ float poll_h_sleep(const float2* p, int epoch) {
    float h; int e;
    asm volatile("ld.relaxed.gpu.global.v2.b32 {%0,%1}, [%2];"
                 : "=f"(h), "=r"(e) : "l"(p));
    while (e != epoch) {
        __nanosleep(100);
        asm volatile("ld.relaxed.gpu.global.v2.b32 {%0,%1}, [%2];"
                     : "=f"(h), "=r"(e) : "l"(p));
    }
    return h;
}
__device__ __forceinline__ void pub_h(float2* p, float h, int epoch) {
    asm volatile("st.relaxed.gpu.global.v2.b32 [%0], {%1,%2};"
                 :: "l"(p), "f"(h), "r"(epoch));
}
__device__ __forceinline__ uint32_t smem_u32(const void* p) {
    uint32_t a;
    asm("{ .reg .u64 t; cvta.to.shared.u64 t, %1; cvt.u32.u64 %0, t; }" : "=r"(a) : "l"(p));
    return a;
}
__device__ __forceinline__ uint32_t mapa_u32(uint32_t addr, uint32_t rank) {
    uint32_t r; asm("mapa.shared::cluster.u32 %0, %1, %2;" : "=r"(r) : "r"(addr), "r"(rank));
    return r;
}
// poll a LOCAL smem {val, epoch} word (critical path: tight loop, no sleep)
__device__ __forceinline__ float poll_local(uint32_t addr, int epoch) {
    uint32_t hb; int e;
    do {
        asm volatile("ld.volatile.shared.v2.b32 {%0,%1}, [%2];"
                     : "=r"(hb), "=r"(e) : "r"(addr));
    } while (e != epoch);
    return __uint_as_float(hb);
}
__device__ __forceinline__ void st_local2(uint32_t addr, float v, int epoch) {
    asm volatile("st.volatile.shared.v2.b32 [%0], {%1,%2};"
                 :: "r"(addr), "r"(__float_as_uint(v)), "r"(epoch) : "memory");
}
__device__ __forceinline__ int ld_local(uint32_t addr) {
    int v; asm volatile("ld.volatile.shared.b32 %0, [%1];" : "=r"(v) : "r"(addr));
    return v;
}
__device__ __forceinline__ void st_local(uint32_t addr, int v) {
    asm volatile("st.volatile.shared.b32 [%0], %1;" :: "r"(addr), "r"(v) : "memory");
}
__device__ __forceinline__ void ffma2(ull& acc, ull a, ull b) {
    asm("fma.rn.f32x2 %0, %1, %2, %0;" : "+l"(acc) : "l"(a), "l"(b));
}
__device__ __forceinline__ ull pack2(float a, float b) {
    ull v; asm("mov.b64 %0, {%1,%2};" : "=l"(v) : "f"(a), "f"(b)); return v;
}
__device__ __forceinline__ ull pack2u(uint32_t a, uint32_t b) {
    ull v; asm("mov.b64 %0, {%1,%2};" : "=l"(v) : "r"(a), "r"(b)); return v;
}
// HW tanh (MUFU.TANH, sm_75+)
__device__ __forceinline__ float tanh_hw(float x) {
    float r; asm("tanh.approx.f32 %0, %1;" : "=f"(r) : "f"(x)); return r;
}

// ---------------- reinit: zero global exchange buffer for the NEXT call ----------------
__global__ void reinit_epochs_kernel() {
    int i = blockIdx.x * blockDim.x + threadIdx.x;   // 1536*512 = 786432
    ((float2*)g_hx)[i] = make_float2(0.0f, 0.0f);
}

// ---------------- pipelined 3-layer LSTM: decoupled consumer/producer ----------------
// grid 48 x 512, cluster (16,1,1) per layer; CTA rank c owns 16 units.
// Consumers (warps 0-7, bar 2): poll local hx word -> h_s[b] -> bar2 ->
//   xg poll (steady-state hit, hoisted before matvec) -> W_hh matvec ->
//   MUFU-tanh gates -> DSMEM push {h,epoch} -> global publish.
// Producers (warps 8-15, bar 1): stage upstream h / x -> bar1 -> W_ih matvec
//   -> backpressure (nanosleep-throttled) -> write self-flagging xg word.
extern "C" __global__ void __launch_bounds__(512, 1)
lstm_pipeline_kernel(
    const float* __restrict__ x,
    const float* __restrict__ wih0, const float* __restrict__ whh0,
    const float* __restrict__ bih0, const float* __restrict__ bhh0,
    const float* __restrict__ wih1, const float* __restrict__ whh1,
    const float* __restrict__ bih1, const float* __restrict__ bhh1,
    const float* __restrict__ wih2, const float* __restrict__ whh2,
    const float* __restrict__ bih2, const float* __restrict__ bhh2)
{
    __shared__ float2 hx_s[2][HID];      // DSMEM push target {h, epoch}
    __shared__ float  h_s [2][HID];      // staged own-layer h(t-1)
    __shared__ float  hup_s[2][HID];     // upstream h / x staging (double-buffered)
    __shared__ float2 xg_s[2][68];       // {xg row val, epoch}, stride 17
    __shared__ int    cons_step_sto;     // consumer progress (volatile)

    const int tid  = threadIdx.x;
    const int l    = blockIdx.x >> 4;
    const int c    = blockIdx.x & 15;    // cluster rank
    const int lane = tid & 31;

    const float* whh = (l == 0) ? whh0 : (l == 1) ? whh1 : whh2;
    const float* wih = (l == 0) ? wih0 : (l == 1) ? wih1 : wih2;
    const float* bih = (l == 0) ? bih0 : (l == 1) ? bih1 : bih2;
    const float* bhh = (l == 0) ? bhh0 : (l == 1) ? bhh1 : bhh2;

    const uint32_t cons_step = smem_u32(&cons_step_sto);

    // ======== consumer state ========
    ull wh[32];
    uint32_t ra0 = 0, ra1 = 0, pa0 = 0, pa1 = 0, xga0 = 0, xga1 = 0;
    int   my_unit = 0, k4c = 0;
    // ======== producer state ========
    ull wi[32];
    float wx[10];
    float pbias = 0.0f;
    int prow = 0, pk4 = 0;
    uint32_t xw0 = 0, xw1 = 0;

    float nl_pre = 0.5f, nl_a = 0.5f, nl_b2 = 0.5f;   // sigmoid via tanh

    if (tid < 256) {
        const int u    = tid >> 5;
        const int hi   = lane >> 4;
        const int gate = (lane >> 2) & 3;
        k4c = lane & 3;
        const int ul = 2 * u + hi;
        const int grow = gate * 256 + c * 16 + ul;
        #pragma unroll
        for (int j = 0; j < 16; j++) {
            const float* pr = whh + grow * HID + 16 * j + 4 * k4c;
            wh[2*j]   = *(const ull*)(pr);
            wh[2*j+1] = *(const ull*)(pr + 2);
        }
        my_unit = c * 16 + ul;
        if (gate == 2) { nl_pre = 1.0f; nl_a = 1.0f; nl_b2 = 0.0f; }  // tanh gate
        ra0 = mapa_u32(smem_u32(&hx_s[0][my_unit]), (uint32_t)(lane & 15));
        ra1 = mapa_u32(smem_u32(&hx_s[1][my_unit]), (uint32_t)(lane & 15));
        pa0 = smem_u32(&hx_s[0][tid]);
        pa1 = smem_u32(&hx_s[1][tid]);
        const int xgi = gate * 17 + ul;
        xga0 = smem_u32(&xg_s[0][xgi]);
        xga1 = smem_u32(&xg_s[1][xgi]);
        if (tid < 64) *(float4*)&h_s[0][tid * 4] = make_float4(0.f, 0.f, 0.f, 0.f);
        if (tid == 0) st_local(cons_step, -1);
    } else {
        const int thr = tid - 256;
        prow = thr >> 2;                 // 0..63 gate row
        pk4  = thr & 3;
        const int pgrow = (prow >> 4) * 256 + c * 16 + (prow & 15);
        pbias = bih[pgrow] + bhh[pgrow];
        const int xgi = (prow >> 4) * 17 + (prow & 15);
        xw0 = smem_u32(&xg_s[0][xgi]);
        xw1 = smem_u32(&xg_s[1][xgi]);
        if (l == 0) {
            #pragma unroll
            for (int j = 0; j < 10; j++) wx[j] = wih[pgrow * F_IN + pk4 * 10 + j];
        } else {
            #pragma unroll
            for (int j = 0; j < 16; j++) {
                const float* pr = wih + pgrow * HID + 16 * j + 4 * pk4;
                wi[2*j]   = *(const ull*)(pr);
                wi[2*j+1] = *(const ull*)(pr + 2);
            }
        }
    }
    __syncthreads();
    asm volatile("barrier.cluster.arrive.aligned;" ::: "memory");
    asm volatile("barrier.cluster.wait.aligned;"   ::: "memory");

    if (tid < 256) {
        // ==================== CONSUMER LOOP ====================
        float cst = 0.0f;                // lanes 0/16: cell state
        for (int t = 0; t < T_STEPS; t++) {
            const int b = t & 1;
            if (t > 0) h_s[b][tid] = poll_local(b ? pa1 : pa0, t);
            asm volatile("bar.sync 2, 256;" ::: "memory");
            if (tid == 0) st_local(cons_step, t);

            // xg hoisted before matvec (steady-state hit; miss overlaps FMAs)
            float xg = poll_local(b ? xga1 : xga0, t + 1);

            // W_hh matvec
            ull a0 = 0ULL, a1 = 0ULL;
            #pragma unroll
            for (int j = 0; j < 16; j++) {
                float4 hv = *(const float4*)&h_s[b][16 * j + 4 * k4c];
                ffma2(a0, wh[2*j],   pack2(hv.x, hv.y));
                ffma2(a1, wh[2*j+1], pack2(hv.z, hv.w));
            }
            float q0, q1, q2, q3;
            asm("mov.b64 {%0,%1}, %2;" : "=f"(q0), "=f"(q1) : "l"(a0));
            asm("mov.b64 {%0,%1}, %2;" : "=f"(q2), "=f"(q3) : "l"(a1));
            float p = (q0 + q1) + (q2 + q3);
            p += __shfl_xor_sync(0xffffffffu, p, 1);
            p += __shfl_xor_sync(0xffffffffu, p, 2);
            p += xg;

            // nonlinearity via MUFU.TANH: i,f,o = 0.5*tanh(0.5x)+0.5; g = tanh(x)
            float th  = tanh_hw(nl_pre * p);
            float val = fmaf(th, nl_a, nl_b2);

            const int base = lane & 16;
            float ff = __shfl_sync(0xffffffffu, val, base + 4);
            float cc = __shfl_sync(0xffffffffu, val, base + 8);
            float oo = __shfl_sync(0xffffffffu, val, base + 12);
            float hn = 0.0f;
            if ((lane & 15) == 0) {
                cst = ff * cst + val * cc;           // val = i on lanes 0/16
                hn  = oo * tanh_hw(cst);
            }
            hn = __shfl_sync(0xffffffffu, hn, base);

            // DSMEM push {h, epoch=t+1} to every rank; then global publish
            ull v = pack2u(__float_as_uint(hn), (uint32_t)(t + 1));
            uint32_t ra = ((t + 1) & 1) ? ra1 : ra0;
            asm volatile("st.shared::cluster.b64 [%0], %1;" :: "r"(ra), "l"(v) : "memory");
            if ((lane & 15) == 0) pub_h(&g_hx[l][t][my_unit], hn, t + 1);
        }
    } else {
        // ==================== PRODUCER LOOP ====================
        const int thr = tid - 256;
        float xr = 0.0f;
        if (l == 0 && thr < F_IN) xr = x[(63 * T_STEPS + 0) * F_IN + thr];

        for (int t = 0; t < T_STEPS; t++) {
            const int b = t & 1;
            // stage upstream h(t) / x(t) into hup_s[b]
            if (l == 0) {
                if (thr < F_IN) {
                    hup_s[b][thr] = xr;
                    if (t + 1 < T_STEPS)
                        xr = x[(63 * T_STEPS + (t + 1)) * F_IN + thr];  // prefetch
                }
            } else {
                hup_s[b][thr] = poll_h_sleep(&g_hx[l-1][t][thr], t + 1);
            }
            asm volatile("bar.sync 1, 256;" ::: "memory");

            // W_ih matvec
            float p = 0.0f;
            if (l == 0) {
                #pragma unroll
                for (int j = 0; j < 10; j++) p = fmaf(wx[j], hup_s[b][pk4 * 10 + j], p);
            } else {
                ull a0 = 0ULL, a1 = 0ULL;
                #pragma unroll
                for (int j = 0; j < 16; j++) {
                    float4 hv = *(const float4*)&hup_s[b][16 * j + 4 * pk4];
                    ffma2(a0, wi[2*j],   pack2(hv.x, hv.y));
                    ffma2(a1, wi[2*j+1], pack2(hv.z, hv.w));
                }
                float q0, q1, q2, q3;
                asm("mov.b64 {%0,%1}, %2;" : "=f"(q0), "=f"(q1) : "l"(a0));
                asm("mov.b64 {%0,%1}, %2;" : "=f"(q2), "=f"(q3) : "l"(a1));
                p = (q0 + q1) + (q2 + q3);
            }
            p += __shfl_xor_sync(0xffffffffu, p, 1);
            p += __shfl_xor_sync(0xffffffffu, p, 2);

            if (pk4 == 0) {
                // backpressure: slot t&1 holds xg(t-2); wait cons_step >= t-1
                if (t >= 2) {
                    while (ld_local(cons_step) < t - 1) { __nanosleep(64); }
                }
                st_local2(b ? xw1 : xw0, p + pbias, t + 1);
            }
        }
    }

    asm volatile("barrier.cluster.arrive.aligned;" ::: "memory");
    asm volatile("barrier.cluster.wait.aligned;"   ::: "memory");
}

// ---------------- classifier: logits = h2 @ W_lin^T + b, log_softmax ----------------
__global__ __launch_bounds__(512, 1) void classifier_kernel(
    const float* __restrict__ wlin,
    const float* __restrict__ blin,
    float* __restrict__ out)
{
    __shared__ float lg[4 * NSPK];
    __shared__ float hsm[4 * HID];
    __shared__ float rbuf[16];

    const int b    = blockIdx.x;
    const int t0   = b * 4;
    const int tid  = threadIdx.x;
    const int lane = tid & 31;
    const int wd   = tid >> 5;

    for (int i = tid; i < 4 * HID; i += 512)
        hsm[i] = g_hx[2][t0 + (i >> 8)][i & 255].x;
    __syncthreads();

    float hr[4][8];
    #pragma unroll
    for (int t = 0; t < 4; t++)
        #pragma unroll
        for (int j = 0; j < 8; j++) hr[t][j] = hsm[t * HID + lane * 8 + j];

    for (int o = wd; o < NSPK; o += 16) {
        const float4* wp = (const float4*)(wlin + o * HID + lane * 8);
        float4 w0 = wp[0], w1 = wp[1];
        float wv[8] = {w0.x, w0.y, w0.z, w0.w, w1.x, w1.y, w1.z, w1.w};
        float a0 = 0.f, a1 = 0.f, a2 = 0.f, a3 = 0.f;
        #pragma unroll
        for (int j = 0; j < 8; j++) {
            float wj = wv[j];
            a0 = fmaf(wj, hr[0][j], a0);
            a1 = fmaf(wj, hr[1][j], a1);
            a2 = fmaf(wj, hr[2][j], a2);
            a3 = fmaf(wj, hr[3][j], a3);
        }
        #pragma unroll
        for (int off = 16; off > 0; off >>= 1) {
            a0 += __shfl_xor_sync(0xffffffffu, a0, off);
            a1 += __shfl_xor_sync(0xffffffffu, a1, off);
            a2 += __shfl_xor_sync(0xffffffffu, a2, off);
            a3 += __shfl_xor_sync(0xffffffffu, a3, off);
        }
        if (lane == 0) {
            float bb = blin[o];
            lg[0 * NSPK + o] = a0 + bb;
            lg[1 * NSPK + o] = a1 + bb;
            lg[2 * NSPK + o] = a2 + bb;
            lg[3 * NSPK + o] = a3 + bb;
        }
    }
    __syncthreads();

    for (int t = 0; t < 4; t++) {
        float m = -1e30f;
        for (int o = tid; o < NSPK; o += 512) m = fmaxf(m, lg[t * NSPK + o]);
        #pragma unroll
        for (int off = 16; off > 0; off >>= 1)
            m = fmaxf(m, __shfl_xor_sync(0xffffffffu, m, off));
        if (lane == 0) rbuf[wd] = m;
        __syncthreads();
        float mm = rbuf[0];
        #pragma unroll
        for (int i = 1; i < 16; i++) mm = fmaxf(mm, rbuf[i]);
        __syncthreads();

        float s = 0.0f;
        for (int o = tid; o < NSPK; o += 512) s += __expf(lg[t * NSPK + o] - mm);
        #pragma unroll
        for (int off = 16; off > 0; off >>= 1)
            s += __shfl_xor_sync(0xffffffffu, s, off);
        if (lane == 0) rbuf[wd] = s;
        __syncthreads();
        float ss = 0.0f;
        #pragma unroll
        for (int i = 0; i < 16; i++) ss += rbuf[i];
        float lse = mm + logf(ss);

        for (int o = tid; o < NSPK; o += 512)
            out[(size_t)(t0 + t) * NSPK + o] = lg[t * NSPK + o] - lse;
        __syncthreads();
    }
}

// ---------------- launch ----------------
extern "C" void kernel_launch(void* const* d_in, const int* in_sizes, int n_in,
                              void* d_out, int out_size)
{
    const float* x    = (const float*)d_in[0];
    const float* wih0 = (const float*)d_in[1];
    const float* whh0 = (const float*)d_in[2];
    const float* bih0 = (const float*)d_in[3];
    const float* bhh0 = (const float*)d_in[4];
    const float* wih1 = (const float*)d_in[5];
    const float* whh1 = (const float*)d_in[6];
    const float* bih1 = (const float*)d_in[7];
    const float* bhh1 = (const float*)d_in[8];
    const float* wih2 = (const float*)d_in[9];
    const float* whh2 = (const float*)d_in[10];
    const float* bih2 = (const float*)d_in[11];
    const float* bhh2 = (const float*)d_in[12];
    const float* wlin = (const float*)d_in[13];
    const float* blin = (const float*)d_in[14];
    float* out = (float*)d_out;

    cudaFuncSetAttribute(lstm_pipeline_kernel,
                         cudaFuncAttributeNonPortableClusterSizeAllowed, 1);

    cudaLaunchConfig_t cfg = {};
    cfg.gridDim  = dim3(48, 1, 1);
    cfg.blockDim = dim3(512, 1, 1);
    cfg.dynamicSmemBytes = 0;
    cfg.stream = 0;
    cudaLaunchAttribute attrs[1];
    attrs[0].id = cudaLaunchAttributeClusterDimension;
    attrs[0].val.clusterDim.x = 16;
    attrs[0].val.clusterDim.y = 1;
    attrs[0].val.clusterDim.z = 1;
    cfg.attrs = attrs;
    cfg.numAttrs = 1;

    cudaLaunchKernelEx(&cfg, lstm_pipeline_kernel, x,
                       wih0, whh0, bih0, bhh0,
                       wih1, whh1, bih1, bhh1,
                       wih2, whh2, bih2, bhh2);

    classifier_kernel<<<256, 512>>>(wlin, blin, out);
    reinit_epochs_kernel<<<1536, 512>>>();
}